// round 1
// baseline (speedup 1.0000x reference)
#include <cuda_runtime.h>
#include <math.h>

#define B 2
#define H 16
#define W 4000
#define PLANE (H*W)          // 64000
#define NPIX (B*PLANE)       // 128000
#define CH 64
#define CDT 80
#define NFLOW 8
#define NLAYER 8

// ---------------- persistent device scratch (static: no allocations) ----------------
__device__ float g_res[B*CH*H*W];                 // residual stream
__device__ float g_skp[B*CH*H*W];                 // skip accumulator
__device__ float g_act[B*CH*H*W];                 // gated activation per layer
__device__ float g_xbuf[2][NPIX];                 // x ping-pong (flipped frames)
__device__ float g_wT [NFLOW*NLAYER*CH*9*128];    // conv weights  [fl][ci][tap][co]
__device__ float g_cwT[NFLOW*NLAYER*CDT*128];     // cond weights  [fl][ci][co]
__device__ float g_uwT[NFLOW*NLAYER*CH*128];      // res|skp wts   [fl][ci][o(0..63 res,64..127 skp)]

// ---------------- weight transpose (runs once per graph replay, ~100us) ----------------
#define N1 (NFLOW*NLAYER*CH*9*128)   // 4718592
#define N2 (NFLOW*NLAYER*CDT*128)    // 655360
#define N3 (NFLOW*NLAYER*CH*128)     // 524288

__global__ void transpose_weights(const float* __restrict__ iw,
                                  const float* __restrict__ cw,
                                  const float* __restrict__ rw,
                                  const float* __restrict__ sw)
{
    long idx = (long)blockIdx.x * 256 + threadIdx.x;
    if (idx < N1) {
        int co  = (int)(idx & 127);
        long t  = idx >> 7;
        int tap = (int)(t % 9); t /= 9;
        int ci  = (int)(t & 63);
        int fl  = (int)(t >> 6);
        int kh = tap / 3, kw = tap % 3;
        g_wT[idx] = iw[((((long)fl*128 + co)*64 + ci)*3 + kh)*3 + kw];
    } else if (idx < N1 + N2) {
        long i2 = idx - N1;
        int co = (int)(i2 & 127);
        long t = i2 >> 7;
        int ci = (int)(t % CDT);
        int fl = (int)(t / CDT);
        g_cwT[i2] = cw[((long)fl*128 + co)*CDT + ci];
    } else if (idx < N1 + N2 + N3) {
        long i3 = idx - N1 - N2;
        int o  = (int)(i3 & 127);
        long t = i3 >> 7;
        int ci = (int)(t & 63);
        int fl = (int)(t >> 6);
        g_uwT[i3] = (o < 64) ? rw[((long)fl*64 + o)*64 + ci]
                             : sw[((long)fl*64 + (o-64))*64 + ci];
    }
}

// ---------------- first causal conv (1->64) + tanh, zero skip ----------------
__global__ void __launch_bounds__(256) first_conv(const float* __restrict__ fw,
                                                  const float* __restrict__ xext,
                                                  int flow)
{
    __shared__ float fsh[128];
    if (threadIdx.x < 128) fsh[threadIdx.x] = fw[threadIdx.x];
    __syncthreads();
    int pix = blockIdx.x * 256 + threadIdx.x;
    if (pix >= NPIX) return;
    int b = pix / PLANE;
    int rem = pix - b * PLANE;
    int h = rem / W;
    int w = rem - h * W;
    const float* xs = (flow == 0) ? xext : g_xbuf[(flow + 1) & 1];
    float x2 = (h >= 2) ? xs[pix - 2*W] : 0.f;
    float x1 = (h >= 1) ? xs[pix - W]   : 0.f;
    #pragma unroll 4
    for (int o = 0; o < 64; o++) {
        float v = tanhf(fsh[2*o] * x2 + fsh[2*o + 1] * x1);
        int idx = ((b*64 + o)*H + h)*W + w;
        g_res[idx] = v;
        g_skp[idx] = 0.f;
    }
}

// ---------------- dilated gated conv: g = conv(res) + cond(c); act = tanh*sigmoid ----------------
// tile: 64 pixels x all 128 g-channels. thread = 4 px (wsub) x 4 channel-pairs (og).
template<int D>
__global__ void __launch_bounds__(256, 2) conv_gate(const float* __restrict__ cin,
                                                    int flow, int fl)
{
    extern __shared__ float sh[];
    float* res_sh = sh;            // 3*64*80 = 15360 floats
    float* w_sh   = sh + 15360;    // 10240 floats (conv chunk / cond weights)

    const int tid  = threadIdx.x;
    const int wsub = tid & 15;
    const int og   = tid >> 4;
    const int bh = blockIdx.y;
    const int b = bh >> 4, h = bh & 15;
    const int w0 = blockIdx.x * 64;

    const float* wT  = g_wT  + (long)fl * (CH*9*128);
    const float* cwT = g_cwT + (long)fl * (CDT*128);

    // load res tile: 3 tap rows (h-2D, h-D, h) x 64 ci x [w0-8, w0+72)
    for (int idx = tid; idx < 3*64*80; idx += 256) {
        int wl = idx % 80;
        int t  = idx / 80;
        int ci = t & 63;
        int r  = t >> 6;
        int hs = h - (2 - r) * D;
        int wg = w0 + wl - 8;
        float v = 0.f;
        if (hs >= 0 && (unsigned)wg < (unsigned)W)
            v = g_res[((b*64 + ci)*H + hs)*W + wg];
        res_sh[idx] = v;
    }

    float accT[4][4];
    float accS[4][4];
    #pragma unroll
    for (int j = 0; j < 4; j++)
        #pragma unroll
        for (int p = 0; p < 4; p++) { accT[j][p] = 0.f; accS[j][p] = 0.f; }

    // main conv: chunks of 8 input channels; weights staged to shared
    for (int cb = 0; cb < 64; cb += 8) {
        __syncthreads();
        {
            const float4* wsrc = (const float4*)(wT + (long)cb * 9 * 128);
            float4* wdst = (float4*)w_sh;
            #pragma unroll
            for (int i = 0; i < 9; i++) wdst[tid + i*256] = wsrc[tid + i*256];
        }
        __syncthreads();
        #pragma unroll 2
        for (int cc = 0; cc < 8; cc++) {
            const int ci = cb + cc;
            const float* wrow = w_sh + cc * (9*128);
            #pragma unroll
            for (int r = 0; r < 3; r++) {
                const float* rp = res_sh + (r*64 + ci)*80 + (wsub << 2);
                float4 winv[5];
                float* win = (float*)winv;
                if (D == 8) {
                    #pragma unroll
                    for (int jj = 0; jj < 5; jj++)
                        winv[jj] = *(const float4*)(rp + 4*jj);
                } else {
                    #pragma unroll
                    for (int jj = 1; jj <= 3; jj++)
                        winv[jj] = *(const float4*)(rp + 4*jj);
                }
                #pragma unroll
                for (int kw = 0; kw < 3; kw++) {
                    float4 wt = *(const float4*)(wrow + (r*3+kw)*128 + (og << 2));
                    float4 ws = *(const float4*)(wrow + (r*3+kw)*128 + (og << 2) + 64);
                    float wtc[4] = {wt.x, wt.y, wt.z, wt.w};
                    float wsc[4] = {ws.x, ws.y, ws.z, ws.w};
                    #pragma unroll
                    for (int p = 0; p < 4; p++) {
                        float xv = win[8 + p + (kw-1)*D];
                        #pragma unroll
                        for (int j = 0; j < 4; j++) {
                            accT[j][p] = fmaf(wtc[j], xv, accT[j][p]);
                            accS[j][p] = fmaf(wsc[j], xv, accS[j][p]);
                        }
                    }
                }
            }
        }
    }

    // conditioner: g += cwT[ci] * c[b,ci,hm,w]  (c accessed through composed flip map)
    __syncthreads();
    {
        const float4* csrc = (const float4*)cwT;
        float4* cdst = (float4*)w_sh;
        #pragma unroll
        for (int i = 0; i < 10; i++) cdst[tid + i*256] = csrc[tid + i*256];
    }
    __syncthreads();

    int hm = h;
    #pragma unroll 1
    for (int j = flow - 1; j >= 0; j--)
        hm = (j < 4) ? (15 - hm) : (hm < 8 ? 7 - hm : 23 - hm);

    const int wpix = w0 + (wsub << 2);
    const bool inb = wpix < W;   // W%4==0 so float4 fully in or out
    #pragma unroll 4
    for (int ci = 0; ci < CDT; ci++) {
        float4 cv = inb ? *(const float4*)(cin + ((long)(b*CDT + ci)*H + hm)*W + wpix)
                        : make_float4(0.f, 0.f, 0.f, 0.f);
        float cvc[4] = {cv.x, cv.y, cv.z, cv.w};
        float4 wt = *(const float4*)(w_sh + ci*128 + (og << 2));
        float4 ws = *(const float4*)(w_sh + ci*128 + (og << 2) + 64);
        float wtc[4] = {wt.x, wt.y, wt.z, wt.w};
        float wsc[4] = {ws.x, ws.y, ws.z, ws.w};
        #pragma unroll
        for (int p = 0; p < 4; p++) {
            #pragma unroll
            for (int j = 0; j < 4; j++) {
                accT[j][p] = fmaf(wtc[j], cvc[p], accT[j][p]);
                accS[j][p] = fmaf(wsc[j], cvc[p], accS[j][p]);
            }
        }
    }

    // act = tanh(g_t) * sigmoid(g_s)
    if (inb) {
        #pragma unroll
        for (int j = 0; j < 4; j++) {
            int co = (og << 2) + j;
            float4 av;
            av.x = tanhf(accT[j][0]) * (1.f / (1.f + expf(-accS[j][0])));
            av.y = tanhf(accT[j][1]) * (1.f / (1.f + expf(-accS[j][1])));
            av.z = tanhf(accT[j][2]) * (1.f / (1.f + expf(-accS[j][2])));
            av.w = tanhf(accT[j][3]) * (1.f / (1.f + expf(-accS[j][3])));
            *(float4*)(g_act + ((b*64 + co)*H + h)*W + wpix) = av;
        }
    }
}

// ---------------- res += rw@act ; skp += sw@act ----------------
__global__ void __launch_bounds__(256) update_kernel(int fl)
{
    __shared__ float u_sh[64*128];
    const int tid  = threadIdx.x;
    const int wsub = tid & 15;
    const int og   = tid >> 4;
    const int bh = blockIdx.y;
    const int b = bh >> 4, h = bh & 15;
    const int w0 = blockIdx.x * 64;

    {
        const float4* usrc = (const float4*)(g_uwT + (long)fl * (CH*128));
        float4* udst = (float4*)u_sh;
        #pragma unroll
        for (int i = 0; i < 8; i++) udst[tid + i*256] = usrc[tid + i*256];
    }
    __syncthreads();

    const int wpix = w0 + (wsub << 2);
    if (wpix >= W) return;

    float aR[4][4], aS[4][4];
    #pragma unroll
    for (int j = 0; j < 4; j++)
        #pragma unroll
        for (int p = 0; p < 4; p++) { aR[j][p] = 0.f; aS[j][p] = 0.f; }

    #pragma unroll 4
    for (int ci = 0; ci < 64; ci++) {
        float4 av = *(const float4*)(g_act + ((b*64 + ci)*H + h)*W + wpix);
        float avc[4] = {av.x, av.y, av.z, av.w};
        float4 wr = *(const float4*)(u_sh + ci*128 + (og << 2));
        float4 wk = *(const float4*)(u_sh + ci*128 + (og << 2) + 64);
        float wrc[4] = {wr.x, wr.y, wr.z, wr.w};
        float wkc[4] = {wk.x, wk.y, wk.z, wk.w};
        #pragma unroll
        for (int p = 0; p < 4; p++) {
            #pragma unroll
            for (int j = 0; j < 4; j++) {
                aR[j][p] = fmaf(wrc[j], avc[p], aR[j][p]);
                aS[j][p] = fmaf(wkc[j], avc[p], aS[j][p]);
            }
        }
    }

    #pragma unroll
    for (int j = 0; j < 4; j++) {
        int o = (og << 2) + j;
        long idx = ((long)(b*64 + o)*H + h)*W + wpix;
        float4 r = *(float4*)(g_res + idx);
        r.x += aR[j][0]; r.y += aR[j][1]; r.z += aR[j][2]; r.w += aR[j][3];
        *(float4*)(g_res + idx) = r;
        float4 s = *(float4*)(g_skp + idx);
        s.x += aS[j][0]; s.y += aS[j][1]; s.z += aS[j][2]; s.w += aS[j][3];
        *(float4*)(g_skp + idx) = s;
    }
}

// ---------------- post: relu->p1->relu->p2, mean/logvar, gm/gl/x update, flip ----------------
__global__ void __launch_bounds__(256) post_kernel(const float* __restrict__ p1,
                                                   const float* __restrict__ p2,
                                                   const float* __restrict__ xext,
                                                   float* __restrict__ out,
                                                   int flow)
{
    __shared__ float p1T[64*64];
    __shared__ float p2s[128];
    for (int i = threadIdx.x; i < 4096; i += 256) {
        int k = i >> 6, j = i & 63;
        p1T[j*64 + k] = p1[i];          // p1T[j][k] = p1[k][j]
    }
    if (threadIdx.x < 128) p2s[threadIdx.x] = p2[threadIdx.x];
    __syncthreads();

    int pix = blockIdx.x * 256 + threadIdx.x;
    if (pix >= NPIX) return;
    int b = pix / PLANE;
    int rem = pix - b * PLANE;
    int h = rem / W;
    int w = rem - h * W;

    float h1[64];
    #pragma unroll
    for (int k = 0; k < 64; k++) h1[k] = 0.f;

    for (int j = 0; j < 64; j++) {
        float s = g_skp[((b*64 + j)*H + h)*W + w];
        s = fmaxf(s, 0.f);
        #pragma unroll
        for (int k = 0; k < 64; k++) h1[k] = fmaf(p1T[j*64 + k], s, h1[k]);
    }
    float o0 = 0.f, o1 = 0.f;
    #pragma unroll
    for (int k = 0; k < 64; k++) {
        float hv = fmaxf(h1[k], 0.f);
        o0 = fmaf(p2s[k], hv, o0);
        o1 = fmaf(p2s[64 + k], hv, o1);
    }
    float mean = o0;
    float lv = fminf(o1, 10.f);
    float e = expf(lv);

    float* gm = out + NPIX;
    float* gl = out + 2*NPIX;
    if (flow == 0) { gm[pix] = mean; gl[pix] = lv; }
    else           { gm[pix] = gm[pix]*e + mean; gl[pix] += lv; }

    const float* xs = (flow == 0) ? xext : g_xbuf[(flow + 1) & 1];
    float xn = e * xs[pix] + mean;
    int hd = (flow < 4) ? (15 - h) : (h < 8 ? 7 - h : 23 - h);
    int odx = b*PLANE + hd*W + w;
    g_xbuf[flow & 1][odx] = xn;
    if (flow == NFLOW - 1) out[odx] = xn;
}

// ---------------- host launcher ----------------
extern "C" void kernel_launch(void* const* d_in, const int* in_sizes, int n_in,
                              void* d_out, int out_size)
{
    const float* x       = (const float*)d_in[0];
    const float* c       = (const float*)d_in[1];
    const float* first_w = (const float*)d_in[2];
    const float* init_w  = (const float*)d_in[3];
    const float* cdt_w   = (const float*)d_in[4];
    const float* res_w   = (const float*)d_in[5];
    const float* skp_w   = (const float*)d_in[6];
    const float* p1      = (const float*)d_in[7];
    const float* p2      = (const float*)d_in[8];
    float* out = (float*)d_out;

    const int CONV_SMEM = (15360 + 10240) * 4;   // 102400 bytes
    cudaFuncSetAttribute(conv_gate<1>, cudaFuncAttributeMaxDynamicSharedMemorySize, CONV_SMEM);
    cudaFuncSetAttribute(conv_gate<2>, cudaFuncAttributeMaxDynamicSharedMemorySize, CONV_SMEM);
    cudaFuncSetAttribute(conv_gate<4>, cudaFuncAttributeMaxDynamicSharedMemorySize, CONV_SMEM);
    cudaFuncSetAttribute(conv_gate<8>, cudaFuncAttributeMaxDynamicSharedMemorySize, CONV_SMEM);

    transpose_weights<<<(N1 + N2 + N3) / 256, 256>>>(init_w, cdt_w, res_w, skp_w);

    dim3 gconv((W + 63) / 64, B * H);   // (63, 32)

    for (int f = 0; f < NFLOW; f++) {
        first_conv<<<(NPIX + 255) / 256, 256>>>(first_w + f * 128, x, f);
        for (int l = 0; l < NLAYER; l++) {
            int d = 1 << (l & 3);
            int fl = f * NLAYER + l;
            switch (d) {
                case 1: conv_gate<1><<<gconv, 256, CONV_SMEM>>>(c, f, fl); break;
                case 2: conv_gate<2><<<gconv, 256, CONV_SMEM>>>(c, f, fl); break;
                case 4: conv_gate<4><<<gconv, 256, CONV_SMEM>>>(c, f, fl); break;
                default: conv_gate<8><<<gconv, 256, CONV_SMEM>>>(c, f, fl); break;
            }
            update_kernel<<<gconv, 256>>>(fl);
        }
        post_kernel<<<(NPIX + 255) / 256, 256>>>(p1 + f * 64 * 64, p2 + f * 2 * 64, x, out, f);
    }
    (void)in_sizes; (void)n_in; (void)out_size;
}

// round 2
// speedup vs baseline: 1.1653x; 1.1653x over previous
#include <cuda_runtime.h>
#include <math.h>

#define B 2
#define H 16
#define W 4000
#define PLANE (H*W)          // 64000
#define NPIX (B*PLANE)       // 128000
#define CH 64
#define CDT 80
#define NFLOW 8
#define NLAYER 8

typedef unsigned long long u64;

// ---- packed fp32x2 helpers (Blackwell FFMA2 path; exact fp32) ----
__device__ __forceinline__ u64 dup2(float x) {
    u64 r; asm("mov.b64 %0, {%1, %1};" : "=l"(r) : "f"(x)); return r;
}
__device__ __forceinline__ void ffma2(u64& d, u64 a, u64 b) {
    asm("fma.rn.f32x2 %0, %1, %2, %0;" : "+l"(d) : "l"(a), "l"(b));
}
__device__ __forceinline__ void unpk(u64 v, float& lo, float& hi) {
    asm("mov.b64 {%0, %1}, %2;" : "=f"(lo), "=f"(hi) : "l"(v));
}

// ---------------- persistent device scratch ----------------
__device__ float g_res2[2][B*CH*H*W];             // residual ping-pong
__device__ float g_skp[B*CH*H*W];                 // skip accumulator
__device__ float g_xbuf[2][NPIX];                 // x ping-pong
__device__ float g_wT [NFLOW*NLAYER*CH*9*128];    // conv weights [fl][ci][tap][co]
__device__ float g_cwT[NFLOW*NLAYER*CDT*128];     // cond weights [fl][ci][co]
__device__ float g_uwT[NFLOW*NLAYER*CH*128];      // res|skp wts  [fl][ci][o]

#define N1 (NFLOW*NLAYER*CH*9*128)
#define N2 (NFLOW*NLAYER*CDT*128)
#define N3 (NFLOW*NLAYER*CH*128)

__global__ void transpose_weights(const float* __restrict__ iw,
                                  const float* __restrict__ cw,
                                  const float* __restrict__ rw,
                                  const float* __restrict__ sw)
{
    long idx = (long)blockIdx.x * 256 + threadIdx.x;
    if (idx < N1) {
        int co  = (int)(idx & 127);
        long t  = idx >> 7;
        int tap = (int)(t % 9); t /= 9;
        int ci  = (int)(t & 63);
        int fl  = (int)(t >> 6);
        int kh = tap / 3, kw = tap % 3;
        g_wT[idx] = iw[((((long)fl*128 + co)*64 + ci)*3 + kh)*3 + kw];
    } else if (idx < N1 + N2) {
        long i2 = idx - N1;
        int co = (int)(i2 & 127);
        long t = i2 >> 7;
        int ci = (int)(t % CDT);
        int fl = (int)(t / CDT);
        g_cwT[i2] = cw[((long)fl*128 + co)*CDT + ci];
    } else if (idx < N1 + N2 + N3) {
        long i3 = idx - N1 - N2;
        int o  = (int)(i3 & 127);
        long t = i3 >> 7;
        int ci = (int)(t & 63);
        int fl = (int)(t >> 6);
        g_uwT[i3] = (o < 64) ? rw[((long)fl*64 + o)*64 + ci]
                             : sw[((long)fl*64 + (o-64))*64 + ci];
    }
}

// ---------------- first causal conv (1->64) + tanh, zero skip ----------------
__global__ void __launch_bounds__(256) first_conv(const float* __restrict__ fw,
                                                  const float* __restrict__ xext,
                                                  int flow)
{
    __shared__ float fsh[128];
    if (threadIdx.x < 128) fsh[threadIdx.x] = fw[threadIdx.x];
    __syncthreads();
    int pix = blockIdx.x * 256 + threadIdx.x;
    if (pix >= NPIX) return;
    int b = pix / PLANE;
    int rem = pix - b * PLANE;
    int h = rem / W;
    int w = rem - h * W;
    const float* xs = (flow == 0) ? xext : g_xbuf[(flow + 1) & 1];
    float x2 = (h >= 2) ? xs[pix - 2*W] : 0.f;
    float x1 = (h >= 1) ? xs[pix - W]   : 0.f;
    #pragma unroll 4
    for (int o = 0; o < 64; o++) {
        float v = tanhf(fsh[2*o] * x2 + fsh[2*o + 1] * x1);
        int idx = ((b*64 + o)*H + h)*W + w;
        g_res2[0][idx] = v;
        g_skp[idx] = 0.f;
    }
}

// ---------------- fused dilated gated conv + cond + res/skip update ----------------
// tile: 64 pixels x 128 g-channels. thread = 4 px (wsub) x 2 co-pairs x {T,S} (og).
// reads res from g_res2[rb], writes updated res to g_res2[rb^1] (no cross-block race).
template<int D>
__global__ void __launch_bounds__(256, 2) conv_gate(const float* __restrict__ cin,
                                                    int flow, int fl, int rb)
{
    extern __shared__ float sh[];
    float* res_sh = sh;            // 3*64*80 = 15360 floats
    float* w_sh   = sh + 15360;    // 10240 floats (conv chunk / cond / update weights)
    float* act_sh = sh;            // reuse of res_sh r=0 area: 64ch x 64px = 4096 floats

    const int tid  = threadIdx.x;
    const int wsub = tid & 15;
    const int og   = tid >> 4;
    const int bh = blockIdx.y;
    const int b = bh >> 4, h = bh & 15;
    const int w0 = blockIdx.x * 64;

    const float* rin  = g_res2[rb];
    float*       rout = g_res2[rb ^ 1];
    const float* wT  = g_wT  + (long)fl * (CH*9*128);
    const float* cwT = g_cwT + (long)fl * (CDT*128);

    // load res tile: 3 tap rows (h-2D, h-D, h) x 64 ci x [w0-8, w0+72)
    for (int idx = tid; idx < 3*64*80; idx += 256) {
        int wl = idx % 80;
        int t  = idx / 80;
        int ci = t & 63;
        int r  = t >> 6;
        int hs = h - (2 - r) * D;
        int wg = w0 + wl - 8;
        float v = 0.f;
        if (hs >= 0 && (unsigned)wg < (unsigned)W)
            v = rin[((b*64 + ci)*H + hs)*W + wg];
        res_sh[idx] = v;
    }

    u64 aT[2][4], aS[2][4];          // [co-pair][px], packed fp32x2
    #pragma unroll
    for (int j = 0; j < 2; j++)
        #pragma unroll
        for (int p = 0; p < 4; p++) { aT[j][p] = 0ull; aS[j][p] = 0ull; }

    // main conv: chunks of 8 input channels; weights staged to shared
    for (int cb = 0; cb < 64; cb += 8) {
        __syncthreads();
        {
            const float4* wsrc = (const float4*)(wT + (long)cb * 9 * 128);
            float4* wdst = (float4*)w_sh;
            #pragma unroll
            for (int i = 0; i < 9; i++) wdst[tid + i*256] = wsrc[tid + i*256];
        }
        __syncthreads();
        #pragma unroll 2
        for (int cc = 0; cc < 8; cc++) {
            const int ci = cb + cc;
            const float* wrow = w_sh + cc * (9*128);
            #pragma unroll
            for (int r = 0; r < 3; r++) {
                const float* rp = res_sh + (r*64 + ci)*80 + (wsub << 2);
                float4 winv[5];
                float* win = (float*)winv;
                if (D == 8) {
                    #pragma unroll
                    for (int jj = 0; jj < 5; jj++)
                        winv[jj] = *(const float4*)(rp + 4*jj);
                } else {
                    #pragma unroll
                    for (int jj = 1; jj <= 3; jj++)
                        winv[jj] = *(const float4*)(rp + 4*jj);
                }
                #pragma unroll
                for (int kw = 0; kw < 3; kw++) {
                    ulonglong2 wt2 = *(const ulonglong2*)(wrow + (r*3+kw)*128 + (og << 2));
                    ulonglong2 ws2 = *(const ulonglong2*)(wrow + (r*3+kw)*128 + (og << 2) + 64);
                    #pragma unroll
                    for (int p = 0; p < 4; p++) {
                        u64 xx = dup2(win[8 + p + (kw-1)*D]);
                        ffma2(aT[0][p], wt2.x, xx);
                        ffma2(aT[1][p], wt2.y, xx);
                        ffma2(aS[0][p], ws2.x, xx);
                        ffma2(aS[1][p], ws2.y, xx);
                    }
                }
            }
        }
    }

    // conditioner: g += cwT[ci] * c[b,ci,hm,w]  (flip map composed analytically)
    __syncthreads();
    {
        const float4* csrc = (const float4*)cwT;
        float4* cdst = (float4*)w_sh;
        #pragma unroll
        for (int i = 0; i < 10; i++) cdst[tid + i*256] = csrc[tid + i*256];
    }
    __syncthreads();

    int hm = h;
    #pragma unroll 1
    for (int j = flow - 1; j >= 0; j--)
        hm = (j < 4) ? (15 - hm) : (hm < 8 ? 7 - hm : 23 - hm);

    const int wpix = w0 + (wsub << 2);
    const bool inb = wpix < W;   // W%4==0 so float4 fully in or out
    #pragma unroll 4
    for (int ci = 0; ci < CDT; ci++) {
        float4 cv = inb ? *(const float4*)(cin + ((long)(b*CDT + ci)*H + hm)*W + wpix)
                        : make_float4(0.f, 0.f, 0.f, 0.f);
        float cvc[4] = {cv.x, cv.y, cv.z, cv.w};
        ulonglong2 wt2 = *(const ulonglong2*)(w_sh + ci*128 + (og << 2));
        ulonglong2 ws2 = *(const ulonglong2*)(w_sh + ci*128 + (og << 2) + 64);
        #pragma unroll
        for (int p = 0; p < 4; p++) {
            u64 xx = dup2(cvc[p]);
            ffma2(aT[0][p], wt2.x, xx);
            ffma2(aT[1][p], wt2.y, xx);
            ffma2(aS[0][p], ws2.x, xx);
            ffma2(aS[1][p], ws2.y, xx);
        }
    }

    // act = tanh(g_t) * sigmoid(g_s) -> stage to shared (act_sh overlays res_sh r=0)
    {
        float t0, t1, s0, s1;
        #pragma unroll
        for (int j = 0; j < 4; j++) {
            float av[4];
            #pragma unroll
            for (int p = 0; p < 4; p++) {
                unpk(aT[j >> 1][p], t0, t1);
                unpk(aS[j >> 1][p], s0, s1);
                float tv = (j & 1) ? t1 : t0;
                float sv = (j & 1) ? s1 : s0;
                av[p] = tanhf(tv) * (1.f / (1.f + expf(-sv)));
            }
            int co = (og << 2) + j;
            *(float4*)(act_sh + co*64 + (wsub << 2)) = make_float4(av[0], av[1], av[2], av[3]);
        }
    }
    __syncthreads();

    // stage update weights [64ci x 128o] into w_sh
    {
        const float4* usrc = (const float4*)(g_uwT + (long)fl * (CH*128));
        float4* udst = (float4*)w_sh;
        #pragma unroll
        for (int i = 0; i < 8; i++) udst[tid + i*256] = usrc[tid + i*256];
    }
    __syncthreads();

    // update: res_out = res_in + rw@act ; skp += sw@act
    u64 aR[2][4], aK[2][4];
    #pragma unroll
    for (int j = 0; j < 2; j++)
        #pragma unroll
        for (int p = 0; p < 4; p++) { aR[j][p] = 0ull; aK[j][p] = 0ull; }

    #pragma unroll 4
    for (int ci = 0; ci < 64; ci++) {
        float4 av = *(const float4*)(act_sh + ci*64 + (wsub << 2));
        float avc[4] = {av.x, av.y, av.z, av.w};
        ulonglong2 wr2 = *(const ulonglong2*)(w_sh + ci*128 + (og << 2));
        ulonglong2 wk2 = *(const ulonglong2*)(w_sh + ci*128 + (og << 2) + 64);
        #pragma unroll
        for (int p = 0; p < 4; p++) {
            u64 xx = dup2(avc[p]);
            ffma2(aR[0][p], wr2.x, xx);
            ffma2(aR[1][p], wr2.y, xx);
            ffma2(aK[0][p], wk2.x, xx);
            ffma2(aK[1][p], wk2.y, xx);
        }
    }

    if (inb) {
        float lo, hi;
        #pragma unroll
        for (int j = 0; j < 4; j++) {
            int o = (og << 2) + j;
            // center row of res_in lives in res_sh r=2 (offset 10240.., untouched by act_sh)
            float4 cr = *(const float4*)(res_sh + (2*64 + o)*80 + 8 + (wsub << 2));
            float4 rv, kv;
            float rr[4], kk[4];
            #pragma unroll
            for (int p = 0; p < 4; p++) {
                unpk(aR[j >> 1][p], lo, hi);
                rr[p] = (j & 1) ? hi : lo;
                unpk(aK[j >> 1][p], lo, hi);
                kk[p] = (j & 1) ? hi : lo;
            }
            rv = make_float4(cr.x + rr[0], cr.y + rr[1], cr.z + rr[2], cr.w + rr[3]);
            long idx = ((long)(b*64 + o)*H + h)*W + wpix;
            *(float4*)(rout + idx) = rv;
            float4 s = *(float4*)(g_skp + idx);
            kv = make_float4(s.x + kk[0], s.y + kk[1], s.z + kk[2], s.w + kk[3]);
            *(float4*)(g_skp + idx) = kv;
        }
    }
}

// ---------------- post: relu->p1->relu->p2, mean/logvar, gm/gl/x update, flip ----------------
__global__ void __launch_bounds__(256) post_kernel(const float* __restrict__ p1,
                                                   const float* __restrict__ p2,
                                                   const float* __restrict__ xext,
                                                   float* __restrict__ out,
                                                   int flow)
{
    __shared__ float p1T[64*64];
    __shared__ float p2s[128];
    for (int i = threadIdx.x; i < 4096; i += 256) {
        int k = i >> 6, j = i & 63;
        p1T[j*64 + k] = p1[i];          // p1T[j][k] = p1[k][j]
    }
    if (threadIdx.x < 128) p2s[threadIdx.x] = p2[threadIdx.x];
    __syncthreads();

    int pix = blockIdx.x * 256 + threadIdx.x;
    if (pix >= NPIX) return;
    int b = pix / PLANE;
    int rem = pix - b * PLANE;
    int h = rem / W;
    int w = rem - h * W;

    u64 h2[32];
    #pragma unroll
    for (int k = 0; k < 32; k++) h2[k] = 0ull;

    for (int j = 0; j < 64; j++) {
        float s = g_skp[((b*64 + j)*H + h)*W + w];
        s = fmaxf(s, 0.f);
        u64 ss = dup2(s);
        const ulonglong2* prow = (const ulonglong2*)(p1T + j*64);
        #pragma unroll
        for (int k2 = 0; k2 < 16; k2++) {
            ulonglong2 wv = prow[k2];
            ffma2(h2[2*k2],     wv.x, ss);
            ffma2(h2[2*k2 + 1], wv.y, ss);
        }
    }
    float o0 = 0.f, o1 = 0.f;
    #pragma unroll
    for (int k = 0; k < 32; k++) {
        float lo, hi;
        unpk(h2[k], lo, hi);
        float h0 = fmaxf(lo, 0.f);
        float h1v = fmaxf(hi, 0.f);
        o0 = fmaf(p2s[2*k], h0, o0);     o0 = fmaf(p2s[2*k+1], h1v, o0);
        o1 = fmaf(p2s[64 + 2*k], h0, o1); o1 = fmaf(p2s[64 + 2*k+1], h1v, o1);
    }
    float mean = o0;
    float lv = fminf(o1, 10.f);
    float e = expf(lv);

    float* gm = out + NPIX;
    float* gl = out + 2*NPIX;
    if (flow == 0) { gm[pix] = mean; gl[pix] = lv; }
    else           { gm[pix] = gm[pix]*e + mean; gl[pix] += lv; }

    const float* xs = (flow == 0) ? xext : g_xbuf[(flow + 1) & 1];
    float xn = e * xs[pix] + mean;
    int hd = (flow < 4) ? (15 - h) : (h < 8 ? 7 - h : 23 - h);
    int odx = b*PLANE + hd*W + w;
    g_xbuf[flow & 1][odx] = xn;
    if (flow == NFLOW - 1) out[odx] = xn;
}

// ---------------- host launcher ----------------
extern "C" void kernel_launch(void* const* d_in, const int* in_sizes, int n_in,
                              void* d_out, int out_size)
{
    const float* x       = (const float*)d_in[0];
    const float* c       = (const float*)d_in[1];
    const float* first_w = (const float*)d_in[2];
    const float* init_w  = (const float*)d_in[3];
    const float* cdt_w   = (const float*)d_in[4];
    const float* res_w   = (const float*)d_in[5];
    const float* skp_w   = (const float*)d_in[6];
    const float* p1      = (const float*)d_in[7];
    const float* p2      = (const float*)d_in[8];
    float* out = (float*)d_out;

    const int CONV_SMEM = (15360 + 10240) * 4;   // 102400 bytes
    cudaFuncSetAttribute(conv_gate<1>, cudaFuncAttributeMaxDynamicSharedMemorySize, CONV_SMEM);
    cudaFuncSetAttribute(conv_gate<2>, cudaFuncAttributeMaxDynamicSharedMemorySize, CONV_SMEM);
    cudaFuncSetAttribute(conv_gate<4>, cudaFuncAttributeMaxDynamicSharedMemorySize, CONV_SMEM);
    cudaFuncSetAttribute(conv_gate<8>, cudaFuncAttributeMaxDynamicSharedMemorySize, CONV_SMEM);

    transpose_weights<<<(N1 + N2 + N3) / 256, 256>>>(init_w, cdt_w, res_w, skp_w);

    dim3 gconv((W + 63) / 64, B * H);   // (63, 32)

    for (int f = 0; f < NFLOW; f++) {
        first_conv<<<(NPIX + 255) / 256, 256>>>(first_w + f * 128, x, f);
        for (int l = 0; l < NLAYER; l++) {
            int d = 1 << (l & 3);
            int fl = f * NLAYER + l;
            int rb = l & 1;
            switch (d) {
                case 1: conv_gate<1><<<gconv, 256, CONV_SMEM>>>(c, f, fl, rb); break;
                case 2: conv_gate<2><<<gconv, 256, CONV_SMEM>>>(c, f, fl, rb); break;
                case 4: conv_gate<4><<<gconv, 256, CONV_SMEM>>>(c, f, fl, rb); break;
                default: conv_gate<8><<<gconv, 256, CONV_SMEM>>>(c, f, fl, rb); break;
            }
        }
        post_kernel<<<(NPIX + 255) / 256, 256>>>(p1 + f * 64 * 64, p2 + f * 2 * 64, x, out, f);
    }
    (void)in_sizes; (void)n_in; (void)out_size;
}